// round 15
// baseline (speedup 1.0000x reference)
#include <cuda_runtime.h>
#include <cuda_bf16.h>
#include <cstdint>

// GRU_39170101739852: B=4096, T=512, H=64 GRU + Linear(H->1), fp32.
// R15: R13 + software-pipelined A-lo fragments (double-buffered ldmatrix,
// prefetch distance 2) and up-front B-fragment loads. Same math/layout.
// 4 engines x 8 batches per 512-thread CTA; Whi in regs, Wlo streamed.

#define TT 512
#define HH 64
#define NTH 512
#define PITCH 144        // bytes per row (72 bf16) in h tiles and Wlo
#define O_WLO 0
#define EB0   27648      // Wlo = 192 rows x 144 B
#define ESTR  6976       // per-engine: h 2x2304 | xt 2112 | red 256
#define SMEMB (EB0 + 4 * ESTR)

__device__ __forceinline__ float ftanh(float v) {
    float r; asm("tanh.approx.f32 %0, %1;" : "=f"(r) : "f"(v)); return r;
}
__device__ __forceinline__ float fsig(float v) {
    return fmaf(0.5f, ftanh(0.5f * v), 0.5f);
}
__device__ __forceinline__ uint32_t pkbf(float a, float b) {
    const __nv_bfloat16 x = __float2bfloat16(a);
    const __nv_bfloat16 y = __float2bfloat16(b);
    return (uint32_t)*(const uint16_t*)&x | ((uint32_t)*(const uint16_t*)&y << 16);
}
__device__ __forceinline__ uint32_t s2u(const void* p) {
    uint32_t a;
    asm("{ .reg .u64 t; cvta.to.shared.u64 t, %1; cvt.u32.u64 %0, t; }"
        : "=r"(a) : "l"(p));
    return a;
}

#define MMA(d, a, bb) \
    asm volatile("mma.sync.aligned.m16n8k16.row.col.f32.bf16.bf16.f32 " \
        "{%0,%1,%2,%3}, {%4,%5,%6,%7}, {%8,%9}, {%0,%1,%2,%3};" \
        : "+f"((d)[0]), "+f"((d)[1]), "+f"((d)[2]), "+f"((d)[3]) \
        : "r"((a)[0]), "r"((a)[1]), "r"((a)[2]), "r"((a)[3]), \
          "r"((bb)[0]), "r"((bb)[1]))

#define LDM4(r, addr) \
    asm volatile("ldmatrix.sync.aligned.m8n8.x4.shared.b16 {%0,%1,%2,%3}, [%4];" \
        : "=r"((r)[0]), "=r"((r)[1]), "=r"((r)[2]), "=r"((r)[3]) : "r"(addr))

// One (mt,ks) group: 2 register-A MMAs + 1 streamed-A MMA, then prefetch
// the A-lo fragment for group i+2 into the buffer just consumed.
#define GROUP_PF(mt, ks, buf, pmt, pks) \
    MMA(acc[mt], ahi[mt][ks], (bh  + 2 * (ks))); \
    MMA(acc[mt], ahi[mt][ks], (bl2 + 2 * (ks))); \
    MMA(acc[mt], buf,          (bh  + 2 * (ks))); \
    LDM4(buf, aloAddr + (pmt) * 9216 + (pks) * 32)

#define GROUP_NP(mt, ks, buf) \
    MMA(acc[mt], ahi[mt][ks], (bh  + 2 * (ks))); \
    MMA(acc[mt], ahi[mt][ks], (bl2 + 2 * (ks))); \
    MMA(acc[mt], buf,          (bh  + 2 * (ks)))

__global__ void __launch_bounds__(NTH, 1)
gru_mma_kernel(const float* __restrict__ x,
               const float* __restrict__ w_ih,
               const float* __restrict__ w_hh,
               const float* __restrict__ b_ih,
               const float* __restrict__ b_hh,
               const float* __restrict__ w_lin,
               const float* __restrict__ b_lin,
               float* __restrict__ out)
{
    extern __shared__ char smem[];
    const int tid  = threadIdx.x;
    const int eng  = tid >> 7;          // engine 0..3, 8 batches each
    const int wt   = tid & 127;
    const int w    = (tid >> 5) & 3;    // warp in engine: units 16w..16w+15
    const int lane = tid & 31;
    const int g    = lane >> 2;
    const int tig  = lane & 3;
    const int bgw  = blockIdx.x * 32 + eng * 8;
    const int barid = eng + 1;

    char*  E   = smem + EB0 + eng * ESTR;
    float* xt  = (float*)(E + 4608);
    float* red = (float*)(E + 6720);

    // ---- fill Wlo tile in smem: [192 rows][pitch 144B] bf16 ----
    for (int i = tid; i < 192 * HH; i += NTH) {
        const int row = i >> 6, k = i & 63;
        const float f = w_hh[row * HH + k];
        const __nv_bfloat16 hi = __float2bfloat16(f);
        *(__nv_bfloat16*)(smem + O_WLO + row * PITCH + k * 2) =
            __float2bfloat16(f - __bfloat162float(hi));
    }
    // zero this engine's h buffers (4608 B = 1152 words)
    for (int i = wt; i < 1152; i += 128) ((uint32_t*)E)[i] = 0u;
    // x chunk 0: 8 rows x 32 t = 64 float4
    if (wt < 64) {
        const int bl = wt >> 3, q = wt & 7;
        const float4 v = *(const float4*)&x[(size_t)(bgw + bl) * TT + q * 4];
        float* xp = xt + bl * 33 + q * 4;
        xp[0] = v.x; xp[1] = v.y; xp[2] = v.z; xp[3] = v.w;
    }

    // ---- Whi fragments (registers) + bias ----
    const int uA = 16 * w + g, uB = uA + 8;
    uint32_t ahi[3][4][4];
    float biasA[3], biasB[3];
    #pragma unroll
    for (int mt = 0; mt < 3; ++mt) {
        const int rA = mt * 64 + uA, rB = mt * 64 + uB;
        biasA[mt] = (mt < 2) ? (b_ih[rA] + b_hh[rA]) : b_hh[rA];
        biasB[mt] = (mt < 2) ? (b_ih[rB] + b_hh[rB]) : b_hh[rB];
        #pragma unroll
        for (int ks = 0; ks < 4; ++ks)
            #pragma unroll
            for (int pos = 0; pos < 4; ++pos) {
                const int row = (pos & 1) ? rB : rA;
                const int col = 16 * ks + 2 * tig + ((pos >> 1) * 8);
                ahi[mt][ks][pos] = pkbf(w_hh[row * HH + col],
                                        w_hh[row * HH + col + 1]);
            }
    }

    // ldmatrix base addresses (u32 shared)
    const uint32_t sbase = s2u(smem);
    const uint32_t aRow = 16 * w + (lane & 7) + 8 * ((lane >> 3) & 1);
    const uint32_t aloAddr = sbase + O_WLO + aRow * PITCH + (lane >> 4) * 16;
    // B: lane -> batch row (l&7), k-block (l>>3)
    const uint32_t hBb  = sbase + (uint32_t)(EB0 + eng * ESTR)
                        + (lane & 7) * PITCH + (lane >> 3) * 16;

    float wir[2], wiz[2], win[2], binv[2], wl[2];
    #pragma unroll
    for (int e = 0; e < 2; ++e) {
        const int u = e ? uB : uA;
        wir[e]  = w_ih[u];
        wiz[e]  = w_ih[HH + u];
        win[e]  = w_ih[2 * HH + u];
        binv[e] = b_ih[2 * HH + u];
        wl[e]   = w_lin[u];
    }
    const float blv = b_lin[0];

    float hp[2][2];   // [e][jj]
    hp[0][0] = hp[0][1] = hp[1][0] = hp[1][1] = 0.0f;

    __syncthreads();

    int p = 0;
    #pragma unroll 1
    for (int t = 0; t < TT; ++t) {
        const uint32_t hrd = hBb + p * 2304;         // read buffer
        char* hwt = E + (p ^ 1) * 2304;              // write buffer

        // ---- seed A-lo prefetch (static addresses), then B fragments ----
        uint32_t la[4], lb[4];
        LDM4(la, aloAddr + 0);        // (mt0,ks0)
        LDM4(lb, aloAddr + 32);       // (mt0,ks1)
        uint32_t bh[8], bl2[8];
        LDM4(bh,      hrd);               // k 0..31
        LDM4(bh + 4,  hrd + 64);          // k 32..63
        LDM4(bl2,     hrd + 1152);
        LDM4(bl2 + 4, hrd + 1152 + 64);

        // ---- acc = bias; pipelined 3-term MMA ----
        float acc[3][4];
        #pragma unroll
        for (int mt = 0; mt < 3; ++mt) {
            acc[mt][0] = biasA[mt]; acc[mt][1] = biasA[mt];
            acc[mt][2] = biasB[mt]; acc[mt][3] = biasB[mt];
        }
        GROUP_PF(0, 0, la, 0, 2);
        GROUP_PF(0, 1, lb, 0, 3);
        GROUP_PF(0, 2, la, 1, 0);
        GROUP_PF(0, 3, lb, 1, 1);
        GROUP_PF(1, 0, la, 1, 2);
        GROUP_PF(1, 1, lb, 1, 3);
        GROUP_PF(1, 2, la, 2, 0);
        GROUP_PF(1, 3, lb, 2, 1);
        GROUP_PF(2, 0, la, 2, 2);
        GROUP_PF(2, 1, lb, 2, 3);
        GROUP_NP(2, 2, la);
        GROUP_NP(2, 3, lb);

        // ---- in-register epilogue: cells (e, jj), batch = 2*tig + jj ----
        const float* xb = xt + ((t >> 5) & 1) * 264;
        const int ttl = t & 31;
        float s[2];
        #pragma unroll
        for (int jj = 0; jj < 2; ++jj) {
            const int b  = 2 * tig + jj;
            const float xv = xb[b * 33 + ttl];
            float sv = 0.0f;
            #pragma unroll
            for (int e = 0; e < 2; ++e) {
                const float ga = acc[0][2 * e + jj];
                const float gz = acc[1][2 * e + jj];
                const float gn = acc[2][2 * e + jj];
                const float r  = fsig(fmaf(wir[e], xv, ga));
                const float z  = fsig(fmaf(wiz[e], xv, gz));
                const float n  = ftanh(fmaf(r, gn, fmaf(win[e], xv, binv[e])));
                const float h  = fmaf(z, hp[e][jj] - n, n);
                hp[e][jj] = h;
                sv = fmaf(wl[e], h, sv);
                const int u = e ? uB : uA;
                const __nv_bfloat16 hb = __float2bfloat16(h);
                *(__nv_bfloat16*)(hwt + b * PITCH + u * 2) = hb;
                *(__nv_bfloat16*)(hwt + 1152 + b * PITCH + u * 2) =
                    __float2bfloat16(h - __bfloat162float(hb));
            }
            s[jj] = sv;
        }

        // ---- output partials: reduce over g ----
        #pragma unroll
        for (int off = 4; off <= 16; off <<= 1) {
            s[0] += __shfl_xor_sync(0xffffffffu, s[0], off);
            s[1] += __shfl_xor_sync(0xffffffffu, s[1], off);
        }
        float* rcur = red + (t & 1) * 32;
        if (g == 0) {
            rcur[(2 * tig + 0) * 4 + w] = s[0];
            rcur[(2 * tig + 1) * 4 + w] = s[1];
        }

        // ---- stage next x chunk ----
        if (((t + 1) & 31) == 0 && (t + 1) < TT && wt < 64) {
            const int bl = wt >> 3, q = wt & 7;
            const float4 v = *(const float4*)&x[(size_t)(bgw + bl) * TT + (t + 1) + q * 4];
            float* xp = xt + (((t + 1) >> 5) & 1) * 264 + bl * 33 + q * 4;
            xp[0] = v.x; xp[1] = v.y; xp[2] = v.z; xp[3] = v.w;
        }

        asm volatile("bar.sync %0, 128;" :: "r"(barid) : "memory");

        if (wt < 8) {
            const float4 r4 = *(const float4*)&rcur[wt * 4];
            out[(size_t)(bgw + wt) * TT + t] = (r4.x + r4.y) + (r4.z + r4.w) + blv;
        }
        p ^= 1;
    }
}

extern "C" void kernel_launch(void* const* d_in, const int* in_sizes, int n_in,
                              void* d_out, int out_size) {
    const float* x     = (const float*)d_in[0];
    const float* w_ih  = (const float*)d_in[1];
    const float* w_hh  = (const float*)d_in[2];
    const float* b_ih  = (const float*)d_in[3];
    const float* b_hh  = (const float*)d_in[4];
    const float* w_lin = (const float*)d_in[5];
    const float* b_lin = (const float*)d_in[6];
    float* out = (float*)d_out;

    cudaFuncSetAttribute(gru_mma_kernel, cudaFuncAttributeMaxDynamicSharedMemorySize,
                         SMEMB);
    gru_mma_kernel<<<128, NTH, SMEMB>>>(x, w_ih, w_hh, b_ih, b_hh,
                                        w_lin, b_lin, out);
}

// round 16
// speedup vs baseline: 1.0259x; 1.0259x over previous
#include <cuda_runtime.h>
#include <cuda_bf16.h>
#include <cstdint>

// GRU_39170101739852: B=4096, T=512, H=64 GRU + Linear(H->1), fp32.
// R16: R13 with the MMA stream reordered acc-interleaved (ks-major) to
// break the 12-deep accumulator RAW chains (same-acc reuse distance 1->3).
// A-lo fragments loaded per-ks, 6 MMAs ahead of first use.
// 4 engines x 8 batches per 512-thread CTA; Whi in regs, Wlo streamed.

#define TT 512
#define HH 64
#define NTH 512
#define PITCH 144        // bytes per row (72 bf16) in h tiles and Wlo
#define O_WLO 0
#define EB0   27648      // Wlo = 192 rows x 144 B
#define ESTR  6976       // per-engine: h 2x2304 | xt 2112 | red 256
#define SMEMB (EB0 + 4 * ESTR)

__device__ __forceinline__ float ftanh(float v) {
    float r; asm("tanh.approx.f32 %0, %1;" : "=f"(r) : "f"(v)); return r;
}
__device__ __forceinline__ float fsig(float v) {
    return fmaf(0.5f, ftanh(0.5f * v), 0.5f);
}
__device__ __forceinline__ uint32_t pkbf(float a, float b) {
    const __nv_bfloat16 x = __float2bfloat16(a);
    const __nv_bfloat16 y = __float2bfloat16(b);
    return (uint32_t)*(const uint16_t*)&x | ((uint32_t)*(const uint16_t*)&y << 16);
}
__device__ __forceinline__ uint32_t s2u(const void* p) {
    uint32_t a;
    asm("{ .reg .u64 t; cvta.to.shared.u64 t, %1; cvt.u32.u64 %0, t; }"
        : "=r"(a) : "l"(p));
    return a;
}

#define MMA(d, a, bb) \
    asm volatile("mma.sync.aligned.m16n8k16.row.col.f32.bf16.bf16.f32 " \
        "{%0,%1,%2,%3}, {%4,%5,%6,%7}, {%8,%9}, {%0,%1,%2,%3};" \
        : "+f"((d)[0]), "+f"((d)[1]), "+f"((d)[2]), "+f"((d)[3]) \
        : "r"((a)[0]), "r"((a)[1]), "r"((a)[2]), "r"((a)[3]), \
          "r"((bb)[0]), "r"((bb)[1]))

#define LDM4(r, addr) \
    asm volatile("ldmatrix.sync.aligned.m8n8.x4.shared.b16 {%0,%1,%2,%3}, [%4];" \
        : "=r"((r)[0]), "=r"((r)[1]), "=r"((r)[2]), "=r"((r)[3]) : "r"(addr))

// One ks block: load 3 A-lo frags, then 9 MMAs rotating acc0->acc1->acc2.
#define KSBLOCK(ks) \
    LDM4(alo0, aloAddr + 0 * 9216 + (ks) * 32); \
    LDM4(alo1, aloAddr + 1 * 9216 + (ks) * 32); \
    LDM4(alo2, aloAddr + 2 * 9216 + (ks) * 32); \
    MMA(acc[0], ahi[0][ks], (bh  + 2 * (ks))); \
    MMA(acc[1], ahi[1][ks], (bh  + 2 * (ks))); \
    MMA(acc[2], ahi[2][ks], (bh  + 2 * (ks))); \
    MMA(acc[0], ahi[0][ks], (bl2 + 2 * (ks))); \
    MMA(acc[1], ahi[1][ks], (bl2 + 2 * (ks))); \
    MMA(acc[2], ahi[2][ks], (bl2 + 2 * (ks))); \
    MMA(acc[0], alo0, (bh + 2 * (ks))); \
    MMA(acc[1], alo1, (bh + 2 * (ks))); \
    MMA(acc[2], alo2, (bh + 2 * (ks)))

__global__ void __launch_bounds__(NTH, 1)
gru_mma_kernel(const float* __restrict__ x,
               const float* __restrict__ w_ih,
               const float* __restrict__ w_hh,
               const float* __restrict__ b_ih,
               const float* __restrict__ b_hh,
               const float* __restrict__ w_lin,
               const float* __restrict__ b_lin,
               float* __restrict__ out)
{
    extern __shared__ char smem[];
    const int tid  = threadIdx.x;
    const int eng  = tid >> 7;          // engine 0..3, 8 batches each
    const int wt   = tid & 127;
    const int w    = (tid >> 5) & 3;    // warp in engine: units 16w..16w+15
    const int lane = tid & 31;
    const int g    = lane >> 2;
    const int tig  = lane & 3;
    const int bgw  = blockIdx.x * 32 + eng * 8;
    const int barid = eng + 1;

    char*  E   = smem + EB0 + eng * ESTR;
    float* xt  = (float*)(E + 4608);
    float* red = (float*)(E + 6720);

    // ---- fill Wlo tile in smem: [192 rows][pitch 144B] bf16 ----
    for (int i = tid; i < 192 * HH; i += NTH) {
        const int row = i >> 6, k = i & 63;
        const float f = w_hh[row * HH + k];
        const __nv_bfloat16 hi = __float2bfloat16(f);
        *(__nv_bfloat16*)(smem + O_WLO + row * PITCH + k * 2) =
            __float2bfloat16(f - __bfloat162float(hi));
    }
    // zero this engine's h buffers (4608 B = 1152 words)
    for (int i = wt; i < 1152; i += 128) ((uint32_t*)E)[i] = 0u;
    // x chunk 0: 8 rows x 32 t = 64 float4
    if (wt < 64) {
        const int bl = wt >> 3, q = wt & 7;
        const float4 v = *(const float4*)&x[(size_t)(bgw + bl) * TT + q * 4];
        float* xp = xt + bl * 33 + q * 4;
        xp[0] = v.x; xp[1] = v.y; xp[2] = v.z; xp[3] = v.w;
    }

    // ---- Whi fragments (registers) + bias ----
    const int uA = 16 * w + g, uB = uA + 8;
    uint32_t ahi[3][4][4];
    float biasA[3], biasB[3];
    #pragma unroll
    for (int mt = 0; mt < 3; ++mt) {
        const int rA = mt * 64 + uA, rB = mt * 64 + uB;
        biasA[mt] = (mt < 2) ? (b_ih[rA] + b_hh[rA]) : b_hh[rA];
        biasB[mt] = (mt < 2) ? (b_ih[rB] + b_hh[rB]) : b_hh[rB];
        #pragma unroll
        for (int ks = 0; ks < 4; ++ks)
            #pragma unroll
            for (int pos = 0; pos < 4; ++pos) {
                const int row = (pos & 1) ? rB : rA;
                const int col = 16 * ks + 2 * tig + ((pos >> 1) * 8);
                ahi[mt][ks][pos] = pkbf(w_hh[row * HH + col],
                                        w_hh[row * HH + col + 1]);
            }
    }

    // ldmatrix base addresses (u32 shared)
    const uint32_t sbase = s2u(smem);
    const uint32_t aRow = 16 * w + (lane & 7) + 8 * ((lane >> 3) & 1);
    const uint32_t aloAddr = sbase + O_WLO + aRow * PITCH + (lane >> 4) * 16;
    // B: lane -> batch row (l&7), k-block (l>>3)
    const uint32_t hBb  = sbase + (uint32_t)(EB0 + eng * ESTR)
                        + (lane & 7) * PITCH + (lane >> 3) * 16;

    float wir[2], wiz[2], win[2], binv[2], wl[2];
    #pragma unroll
    for (int e = 0; e < 2; ++e) {
        const int u = e ? uB : uA;
        wir[e]  = w_ih[u];
        wiz[e]  = w_ih[HH + u];
        win[e]  = w_ih[2 * HH + u];
        binv[e] = b_ih[2 * HH + u];
        wl[e]   = w_lin[u];
    }
    const float blv = b_lin[0];

    float hp[2][2];   // [e][jj]
    hp[0][0] = hp[0][1] = hp[1][0] = hp[1][1] = 0.0f;

    __syncthreads();

    int p = 0;
    #pragma unroll 1
    for (int t = 0; t < TT; ++t) {
        const uint32_t hrd = hBb + p * 2304;         // read buffer
        char* hwt = E + (p ^ 1) * 2304;              // write buffer

        // ---- B fragments up front ----
        uint32_t bh[8], bl2[8];
        LDM4(bh,      hrd);               // k 0..31
        LDM4(bh + 4,  hrd + 64);          // k 32..63
        LDM4(bl2,     hrd + 1152);
        LDM4(bl2 + 4, hrd + 1152 + 64);

        // ---- acc = bias; acc-interleaved 3-term MMA ----
        float acc[3][4];
        #pragma unroll
        for (int mt = 0; mt < 3; ++mt) {
            acc[mt][0] = biasA[mt]; acc[mt][1] = biasA[mt];
            acc[mt][2] = biasB[mt]; acc[mt][3] = biasB[mt];
        }
        uint32_t alo0[4], alo1[4], alo2[4];
        KSBLOCK(0);
        KSBLOCK(1);
        KSBLOCK(2);
        KSBLOCK(3);

        // ---- in-register epilogue: cells (e, jj), batch = 2*tig + jj ----
        const float* xb = xt + ((t >> 5) & 1) * 264;
        const int ttl = t & 31;
        float s[2];
        #pragma unroll
        for (int jj = 0; jj < 2; ++jj) {
            const int b  = 2 * tig + jj;
            const float xv = xb[b * 33 + ttl];
            float sv = 0.0f;
            #pragma unroll
            for (int e = 0; e < 2; ++e) {
                const float ga = acc[0][2 * e + jj];
                const float gz = acc[1][2 * e + jj];
                const float gn = acc[2][2 * e + jj];
                const float r  = fsig(fmaf(wir[e], xv, ga));
                const float z  = fsig(fmaf(wiz[e], xv, gz));
                const float n  = ftanh(fmaf(r, gn, fmaf(win[e], xv, binv[e])));
                const float h  = fmaf(z, hp[e][jj] - n, n);
                hp[e][jj] = h;
                sv = fmaf(wl[e], h, sv);
                const int u = e ? uB : uA;
                const __nv_bfloat16 hb = __float2bfloat16(h);
                *(__nv_bfloat16*)(hwt + b * PITCH + u * 2) = hb;
                *(__nv_bfloat16*)(hwt + 1152 + b * PITCH + u * 2) =
                    __float2bfloat16(h - __bfloat162float(hb));
            }
            s[jj] = sv;
        }

        // ---- output partials: reduce over g ----
        #pragma unroll
        for (int off = 4; off <= 16; off <<= 1) {
            s[0] += __shfl_xor_sync(0xffffffffu, s[0], off);
            s[1] += __shfl_xor_sync(0xffffffffu, s[1], off);
        }
        float* rcur = red + (t & 1) * 32;
        if (g == 0) {
            rcur[(2 * tig + 0) * 4 + w] = s[0];
            rcur[(2 * tig + 1) * 4 + w] = s[1];
        }

        // ---- stage next x chunk ----
        if (((t + 1) & 31) == 0 && (t + 1) < TT && wt < 64) {
            const int bl = wt >> 3, q = wt & 7;
            const float4 v = *(const float4*)&x[(size_t)(bgw + bl) * TT + (t + 1) + q * 4];
            float* xp = xt + (((t + 1) >> 5) & 1) * 264 + bl * 33 + q * 4;
            xp[0] = v.x; xp[1] = v.y; xp[2] = v.z; xp[3] = v.w;
        }

        asm volatile("bar.sync %0, 128;" :: "r"(barid) : "memory");

        if (wt < 8) {
            const float4 r4 = *(const float4*)&rcur[wt * 4];
            out[(size_t)(bgw + wt) * TT + t] = (r4.x + r4.y) + (r4.z + r4.w) + blv;
        }
        p ^= 1;
    }
}

extern "C" void kernel_launch(void* const* d_in, const int* in_sizes, int n_in,
                              void* d_out, int out_size) {
    const float* x     = (const float*)d_in[0];
    const float* w_ih  = (const float*)d_in[1];
    const float* w_hh  = (const float*)d_in[2];
    const float* b_ih  = (const float*)d_in[3];
    const float* b_hh  = (const float*)d_in[4];
    const float* w_lin = (const float*)d_in[5];
    const float* b_lin = (const float*)d_in[6];
    float* out = (float*)d_out;

    cudaFuncSetAttribute(gru_mma_kernel, cudaFuncAttributeMaxDynamicSharedMemorySize,
                         SMEMB);
    gru_mma_kernel<<<128, NTH, SMEMB>>>(x, w_ih, w_hh, b_ih, b_hh,
                                        w_lin, b_lin, out);
}

// round 17
// speedup vs baseline: 1.3395x; 1.3057x over previous
#include <cuda_runtime.h>
#include <cuda_fp16.h>
#include <cstdint>

// GRU_39170101739852: B=4096, T=512, H=64 GRU + Linear(H->1), fp32.
// R17: fp16 2-term split-precision MMA. W single fp16 (registers, 11-bit
// mantissa); h split fp16 hi+lo in smem. Eliminates the entire Wlo stream
// (12 LDM4 + 12 MMAs per warp per step). 4 engines x 8 batches, 512 thr.

#define TT 512
#define HH 64
#define NTH 512
#define PITCH 144        // bytes per row (72 fp16) in h tiles
#define ESTR  6976       // per-engine: h 2x2304 | xt 2112 | red 256
#define SMEMB (4 * ESTR)

__device__ __forceinline__ float ftanh(float v) {
    float r; asm("tanh.approx.f32 %0, %1;" : "=f"(r) : "f"(v)); return r;
}
__device__ __forceinline__ float fsig(float v) {
    return fmaf(0.5f, ftanh(0.5f * v), 0.5f);
}
__device__ __forceinline__ uint32_t pkhf(float a, float b) {
    const __half x = __float2half_rn(a);
    const __half y = __float2half_rn(b);
    return (uint32_t)*(const uint16_t*)&x | ((uint32_t)*(const uint16_t*)&y << 16);
}
__device__ __forceinline__ uint32_t s2u(const void* p) {
    uint32_t a;
    asm("{ .reg .u64 t; cvta.to.shared.u64 t, %1; cvt.u32.u64 %0, t; }"
        : "=r"(a) : "l"(p));
    return a;
}

#define MMA(d, a, bb) \
    asm volatile("mma.sync.aligned.m16n8k16.row.col.f32.f16.f16.f32 " \
        "{%0,%1,%2,%3}, {%4,%5,%6,%7}, {%8,%9}, {%0,%1,%2,%3};" \
        : "+f"((d)[0]), "+f"((d)[1]), "+f"((d)[2]), "+f"((d)[3]) \
        : "r"((a)[0]), "r"((a)[1]), "r"((a)[2]), "r"((a)[3]), \
          "r"((bb)[0]), "r"((bb)[1]))

#define LDM4(r, addr) \
    asm volatile("ldmatrix.sync.aligned.m8n8.x4.shared.b16 {%0,%1,%2,%3}, [%4];" \
        : "=r"((r)[0]), "=r"((r)[1]), "=r"((r)[2]), "=r"((r)[3]) : "r"(addr))

// One ks block: 6 MMAs rotating acc0->acc1->acc2 (terms W*hhi, W*hlo).
#define KSBLOCK(ks) \
    MMA(acc[0], ahi[0][ks], (bh  + 2 * (ks))); \
    MMA(acc[1], ahi[1][ks], (bh  + 2 * (ks))); \
    MMA(acc[2], ahi[2][ks], (bh  + 2 * (ks))); \
    MMA(acc[0], ahi[0][ks], (bl2 + 2 * (ks))); \
    MMA(acc[1], ahi[1][ks], (bl2 + 2 * (ks))); \
    MMA(acc[2], ahi[2][ks], (bl2 + 2 * (ks)))

__global__ void __launch_bounds__(NTH, 1)
gru_mma_kernel(const float* __restrict__ x,
               const float* __restrict__ w_ih,
               const float* __restrict__ w_hh,
               const float* __restrict__ b_ih,
               const float* __restrict__ b_hh,
               const float* __restrict__ w_lin,
               const float* __restrict__ b_lin,
               float* __restrict__ out)
{
    extern __shared__ char smem[];
    const int tid  = threadIdx.x;
    const int eng  = tid >> 7;          // engine 0..3, 8 batches each
    const int wt   = tid & 127;
    const int w    = (tid >> 5) & 3;    // warp in engine: units 16w..16w+15
    const int lane = tid & 31;
    const int g    = lane >> 2;
    const int tig  = lane & 3;
    const int bgw  = blockIdx.x * 32 + eng * 8;
    const int barid = eng + 1;

    char*  E   = smem + eng * ESTR;
    float* xt  = (float*)(E + 4608);
    float* red = (float*)(E + 6720);

    // zero this engine's h buffers (4608 B = 1152 words)
    for (int i = wt; i < 1152; i += 128) ((uint32_t*)E)[i] = 0u;
    // x chunk 0: 8 rows x 32 t = 64 float4
    if (wt < 64) {
        const int bl = wt >> 3, q = wt & 7;
        const float4 v = *(const float4*)&x[(size_t)(bgw + bl) * TT + q * 4];
        float* xp = xt + bl * 33 + q * 4;
        xp[0] = v.x; xp[1] = v.y; xp[2] = v.z; xp[3] = v.w;
    }

    // ---- W fragments (fp16, registers) + bias ----
    const int uA = 16 * w + g, uB = uA + 8;
    uint32_t ahi[3][4][4];
    float biasA[3], biasB[3];
    #pragma unroll
    for (int mt = 0; mt < 3; ++mt) {
        const int rA = mt * 64 + uA, rB = mt * 64 + uB;
        biasA[mt] = (mt < 2) ? (b_ih[rA] + b_hh[rA]) : b_hh[rA];
        biasB[mt] = (mt < 2) ? (b_ih[rB] + b_hh[rB]) : b_hh[rB];
        #pragma unroll
        for (int ks = 0; ks < 4; ++ks)
            #pragma unroll
            for (int pos = 0; pos < 4; ++pos) {
                const int row = (pos & 1) ? rB : rA;
                const int col = 16 * ks + 2 * tig + ((pos >> 1) * 8);
                ahi[mt][ks][pos] = pkhf(w_hh[row * HH + col],
                                        w_hh[row * HH + col + 1]);
            }
    }

    // B ldmatrix base: lane -> batch row (l&7), k-block (l>>3)
    const uint32_t sbase = s2u(smem);
    const uint32_t hBb  = sbase + (uint32_t)(eng * ESTR)
                        + (lane & 7) * PITCH + (lane >> 3) * 16;

    float wir[2], wiz[2], win[2], binv[2], wl[2];
    #pragma unroll
    for (int e = 0; e < 2; ++e) {
        const int u = e ? uB : uA;
        wir[e]  = w_ih[u];
        wiz[e]  = w_ih[HH + u];
        win[e]  = w_ih[2 * HH + u];
        binv[e] = b_ih[2 * HH + u];
        wl[e]   = w_lin[u];
    }
    const float blv = b_lin[0];

    float hp[2][2];   // [e][jj]
    hp[0][0] = hp[0][1] = hp[1][0] = hp[1][1] = 0.0f;

    __syncthreads();

    int p = 0;
    #pragma unroll 1
    for (int t = 0; t < TT; ++t) {
        const uint32_t hrd = hBb + p * 2304;         // read buffer
        char* hwt = E + (p ^ 1) * 2304;              // write buffer

        // ---- B fragments: h hi (2x ldmatrix.x4), h lo (2x) ----
        uint32_t bh[8], bl2[8];
        LDM4(bh,      hrd);               // k 0..31
        LDM4(bh + 4,  hrd + 64);          // k 32..63
        LDM4(bl2,     hrd + 1152);
        LDM4(bl2 + 4, hrd + 1152 + 64);

        // ---- acc = bias; 2-term MMA, acc-interleaved ----
        float acc[3][4];
        #pragma unroll
        for (int mt = 0; mt < 3; ++mt) {
            acc[mt][0] = biasA[mt]; acc[mt][1] = biasA[mt];
            acc[mt][2] = biasB[mt]; acc[mt][3] = biasB[mt];
        }
        KSBLOCK(0);
        KSBLOCK(1);
        KSBLOCK(2);
        KSBLOCK(3);

        // ---- in-register epilogue: cells (e, jj), batch = 2*tig + jj ----
        const float* xb = xt + ((t >> 5) & 1) * 264;
        const int ttl = t & 31;
        float s[2];
        #pragma unroll
        for (int jj = 0; jj < 2; ++jj) {
            const int b  = 2 * tig + jj;
            const float xv = xb[b * 33 + ttl];
            float sv = 0.0f;
            #pragma unroll
            for (int e = 0; e < 2; ++e) {
                const float ga = acc[0][2 * e + jj];
                const float gz = acc[1][2 * e + jj];
                const float gn = acc[2][2 * e + jj];
                const float r  = fsig(fmaf(wir[e], xv, ga));
                const float z  = fsig(fmaf(wiz[e], xv, gz));
                const float n  = ftanh(fmaf(r, gn, fmaf(win[e], xv, binv[e])));
                const float h  = fmaf(z, hp[e][jj] - n, n);
                hp[e][jj] = h;
                sv = fmaf(wl[e], h, sv);
                const int u = e ? uB : uA;
                const __half hb = __float2half_rn(h);
                *(__half*)(hwt + b * PITCH + u * 2) = hb;
                *(__half*)(hwt + 1152 + b * PITCH + u * 2) =
                    __float2half_rn(h - __half2float(hb));
            }
            s[jj] = sv;
        }

        // ---- output partials: reduce over g ----
        #pragma unroll
        for (int off = 4; off <= 16; off <<= 1) {
            s[0] += __shfl_xor_sync(0xffffffffu, s[0], off);
            s[1] += __shfl_xor_sync(0xffffffffu, s[1], off);
        }
        float* rcur = red + (t & 1) * 32;
        if (g == 0) {
            rcur[(2 * tig + 0) * 4 + w] = s[0];
            rcur[(2 * tig + 1) * 4 + w] = s[1];
        }

        // ---- stage next x chunk ----
        if (((t + 1) & 31) == 0 && (t + 1) < TT && wt < 64) {
            const int bl = wt >> 3, q = wt & 7;
            const float4 v = *(const float4*)&x[(size_t)(bgw + bl) * TT + (t + 1) + q * 4];
            float* xp = xt + (((t + 1) >> 5) & 1) * 264 + bl * 33 + q * 4;
            xp[0] = v.x; xp[1] = v.y; xp[2] = v.z; xp[3] = v.w;
        }

        asm volatile("bar.sync %0, 128;" :: "r"(barid) : "memory");

        if (wt < 8) {
            const float4 r4 = *(const float4*)&rcur[wt * 4];
            out[(size_t)(bgw + wt) * TT + t] = (r4.x + r4.y) + (r4.z + r4.w) + blv;
        }
        p ^= 1;
    }
}

extern "C" void kernel_launch(void* const* d_in, const int* in_sizes, int n_in,
                              void* d_out, int out_size) {
    const float* x     = (const float*)d_in[0];
    const float* w_ih  = (const float*)d_in[1];
    const float* w_hh  = (const float*)d_in[2];
    const float* b_ih  = (const float*)d_in[3];
    const float* b_hh  = (const float*)d_in[4];
    const float* w_lin = (const float*)d_in[5];
    const float* b_lin = (const float*)d_in[6];
    float* out = (float*)d_out;

    cudaFuncSetAttribute(gru_mma_kernel, cudaFuncAttributeMaxDynamicSharedMemorySize,
                         SMEMB);
    gru_mma_kernel<<<128, NTH, SMEMB>>>(x, w_ih, w_hh, b_ih, b_hh,
                                        w_lin, b_lin, out);
}